// round 12
// baseline (speedup 1.0000x reference)
#include <cuda_runtime.h>
#include <cuda_bf16.h>
#include <math.h>

// Problem shape (fixed by the dataset):
//   B=64, T=512, D_in=256, D_out=1024, M=8 (module_size=128)
// KEY STRUCTURE: h@W_h never mixes batch rows -> the 64 sequences are
// independent. Phase 2 uses 4 INDEPENDENT row-groups of 32 CTAs each
// (CTA = 16 rows x 32 cols, full K). Warp = one batch row: stages its 4KB
// h-row into private smem, runs a pure-LDS FFMA2 k-loop (no split-K, no
// cross-warp reduction), shfl-butterfly tail, 32-CTA per-group barrier.

#define B_      64
#define T_      512
#define DIN     256
#define DOUT    1024
#define BSTR    ((size_t)T_ * DOUT)
#define YS_ELEMS ((size_t)B_ * T_ * DOUT)

typedef unsigned long long ull;

// ---------------------------------------------------------------------------
// Packed-fp32 helpers (Blackwell f32x2)
// ---------------------------------------------------------------------------
__device__ __forceinline__ ull dupf(float x) {
    ull r;
    asm("mov.b64 %0, {%1, %1};" : "=l"(r) : "f"(x));
    return r;
}
__device__ __forceinline__ void ffma2(ull& d, ull a, ull b) {
    asm("fma.rn.f32x2 %0, %1, %2, %0;" : "+l"(d) : "l"(a), "l"(b));
}
__device__ __forceinline__ ull addf2(ull a, ull b) {
    ull r;
    asm("add.rn.f32x2 %0, %1, %2;" : "=l"(r) : "l"(a), "l"(b));
    return r;
}
__device__ __forceinline__ float2 unpk(ull v) {
    float2 r;
    asm("mov.b64 {%0, %1}, %2;" : "=f"(r.x), "=f"(r.y) : "l"(v));
    return r;
}
__device__ __forceinline__ ull shflx64(ull v, int off) {
    return __shfl_xor_sync(0xffffffffu, v, off);
}

// ---------------------------------------------------------------------------
// Phase 1: u = X @ W_in + b_in     (M=32768, N=1024, K=256)  [unchanged]
// ---------------------------------------------------------------------------
__global__ void __launch_bounds__(256) phase1_gemm(
    const float* __restrict__ X, const float* __restrict__ Win,
    const float* __restrict__ bin, float* __restrict__ out)
{
    __shared__ float As[16 * 132];
    __shared__ float Bs[16 * 68];

    const int tid = threadIdx.x;
    const int tn0 = blockIdx.x * 64;
    const int tm0 = blockIdx.y * 128;
    const int ty  = tid >> 4;
    const int tx  = tid & 15;

    ull acc01[8], acc23[8];
#pragma unroll
    for (int i = 0; i < 8; i++) { acc01[i] = 0ull; acc23[i] = 0ull; }

    const int arow  = tid >> 1;
    const int akoff = (tid & 1) * 8;
    const int bk    = tid >> 4;
    const int bn    = (tid & 15) * 4;

    for (int kc = 0; kc < DIN; kc += 16) {
        const float* ap = &X[(size_t)(tm0 + arow) * DIN + kc + akoff];
        float4 a0 = *(const float4*)(ap);
        float4 a1 = *(const float4*)(ap + 4);
        float4 b0 = *(const float4*)&Win[(size_t)(kc + bk) * DOUT + tn0 + bn];

        __syncthreads();
        As[(akoff + 0) * 132 + arow] = a0.x;
        As[(akoff + 1) * 132 + arow] = a0.y;
        As[(akoff + 2) * 132 + arow] = a0.z;
        As[(akoff + 3) * 132 + arow] = a0.w;
        As[(akoff + 4) * 132 + arow] = a1.x;
        As[(akoff + 5) * 132 + arow] = a1.y;
        As[(akoff + 6) * 132 + arow] = a1.z;
        As[(akoff + 7) * 132 + arow] = a1.w;
        *(float4*)&Bs[bk * 68 + bn] = b0;
        __syncthreads();

#pragma unroll
        for (int kk = 0; kk < 16; kk++) {
            float4 af0 = *(const float4*)&As[kk * 132 + ty * 8];
            float4 af1 = *(const float4*)&As[kk * 132 + ty * 8 + 4];
            ulonglong2 bb = *(const ulonglong2*)&Bs[kk * 68 + tx * 4];
            float a[8] = {af0.x, af0.y, af0.z, af0.w, af1.x, af1.y, af1.z, af1.w};
#pragma unroll
            for (int i = 0; i < 8; i++) {
                ull ad = dupf(a[i]);
                ffma2(acc01[i], ad, bb.x);
                ffma2(acc23[i], ad, bb.y);
            }
        }
    }

    ulonglong2 bp = *(const ulonglong2*)&bin[tn0 + tx * 4];
#pragma unroll
    for (int i = 0; i < 8; i++) {
        ulonglong2 st;
        st.x = addf2(acc01[i], bp.x);
        st.y = addf2(acc23[i], bp.y);
        *(ulonglong2*)&out[(size_t)(tm0 + ty * 8 + i) * DOUT + tn0 + tx * 4] = st;
    }
}

// ---------------------------------------------------------------------------
// Phase 2: 4 independent row-groups x 32 CTAs. CTA (rowg=bid>>5, colg=bid&31)
// owns rows [16*rowg,+16) x cols [32*colg,+32). Warp w = row r0+w.
// ---------------------------------------------------------------------------
#define NB2 128
#define WPITCH 36                      // floats per k-row of sW (32 + 4 pad)
#define HPITCH 1028                    // floats per h row (1024 + 4 pad)
#define SMEM2 ((1024 * WPITCH + 16 * HPITCH) * 4)   // 213248 B

// Hidden state, double-buffered by t parity: g_h[buf][r*1024 + j], row-major.
__device__ float g_h[2][B_ * DOUT];

// Per-CTA flags (128B apart) + per-group release words (128B apart).
__device__ volatile unsigned g_flag[NB2 * 32];
__device__ volatile unsigned g_gen2[4 * 32];

// 32-CTA group barrier. CTA stores its step to a private flag; group leader
// (colg==0) polls its group's 32 flags (one per lane) and releases a single
// per-group word. Equality compares + strictly increasing targets => safe
// across graph replays (stale 512 never equals a fresh target first time).
__device__ __forceinline__ void gsync(int bid, int rowg, int colg, unsigned target)
{
    __syncthreads();
    if (threadIdx.x == 0) {
        __threadfence();
        g_flag[bid << 5] = target;
    }
    if (colg == 0) {
        if (threadIdx.x < 32) {
            const int fi = ((rowg << 5) + (int)threadIdx.x) << 5;
            while (g_flag[fi] != target) { }
            __syncwarp();
            if (threadIdx.x == 0) {
                __threadfence();
                g_gen2[rowg << 5] = target;
            }
        }
    } else if (threadIdx.x == 0) {
        while (g_gen2[rowg << 5] != target) { }
        __threadfence();
    }
    __syncthreads();
}

__global__ void __launch_bounds__(512, 1) phase2_rnn(
    const float* __restrict__ Wh, const float* __restrict__ periods,
    const float* __restrict__ shifts, float* __restrict__ out)
{
    extern __shared__ float smf[];
    float* sW = smf;                       // [k][WPITCH]: W_h[k][j0+0..31]
    float* sH = smf + 1024 * WPITCH;       // [16 warps][HPITCH]: h row

    const int tid  = threadIdx.x;
    const int bid  = blockIdx.x;
    const int rowg = bid >> 5;
    const int colg = bid & 31;
    const int j0   = colg * 32;            // first of 32 cols
    const int r0   = rowg * 16;            // first of 16 rows
    const int w    = tid >> 5;             // warp -> row r0+w
    const int l    = tid & 31;
    const int p4   = l & 3;                // lane's pair block (pairs 4p4..4p4+3)
    const int q    = l >> 2;               // lane's k-phase (k = kb+q, kb step 8)
    const int gr   = r0 + w;               // global batch row

    // One-time: stage this CTA's 32 W_h columns, k-major with padded pitch.
    for (int i = tid; i < 1024 * 32; i += 512) {
        int k = i >> 5, j = i & 31;
        sW[k * WPITCH + j] = Wh[(size_t)k * DOUT + j0 + j];
    }
    const float per = periods[colg >> 2];  // 32 cols lie inside one module
    const float shf = shifts[colg >> 2];

    // Epilogue mapping: lanes 0..15 each own one col-pair.
    const int sel = l & 15;                // pair index
    const int src = sel >> 2;              // lane holding that pair's acc
    const int ej  = j0 + 2 * sel;          // global col of pair
    float* hrW = sH + w * HPITCH;
    __syncthreads();

    // ---- t = 0: h_prev = 0 -> y = (1-g) * tanh(u). ----
    if (l < 16) {
        float g0 = (sinf(shf) + 1.f) * 0.5f;
        size_t ob = (size_t)gr * BSTR + ej;
        float2 u = *(const float2*)&out[ob];
        float2 y;
        y.x = (1.f - g0) * tanhf(u.x);
        y.y = (1.f - g0) * tanhf(u.y);
        *(float2*)&out[ob] = y;
        *(float2*)&g_h[0][gr * DOUT + ej] = y;
    }
    gsync(bid, rowg, colg, 1u);

    const float* wbase = sW + q * WPITCH + p4 * 8;  // this lane's W stream

    for (int t = 1; t < T_; t++) {
        // Hoisted u load (independent of h).
        size_t ob = 0; float2 uv = make_float2(0.f, 0.f);
        if (l < 16) {
            ob = (size_t)gr * BSTR + (size_t)t * DOUT + ej;
            uv = *(const float2*)&out[ob];
        }

        // Stage h_prev row (4KB) into this warp's private smem row.
        const float* hsrc = g_h[(t - 1) & 1] + gr * DOUT;
#pragma unroll
        for (int j = 0; j < 8; j++) {
            float4 v = __ldcg((const float4*)(hsrc + j * 128 + (l << 2)));
            *(float4*)(hrW + j * 128 + (l << 2)) = v;
        }
        __syncwarp();

        // Mainloop: pure-LDS. Lane: k = kb+q, pairs 4p4..4p4+3.
        const float* hrq = hrW + q;
        ull a0 = 0, a1 = 0, a2 = 0, a3 = 0;
#pragma unroll 8
        for (int kb = 0; kb < 1024; kb += 8) {
            float hq = hrq[kb];                            // LDS.32 (broadcast x4)
            const float* wp = wbase + kb * WPITCH;
            ulonglong2 wA = *(const ulonglong2*)(wp);      // pairs 4p4, 4p4+1
            ulonglong2 wB = *(const ulonglong2*)(wp + 4);  // pairs 4p4+2, 4p4+3
            ull hd = dupf(hq);
            ffma2(a0, hd, wA.x); ffma2(a1, hd, wA.y);
            ffma2(a2, hd, wB.x); ffma2(a3, hd, wB.y);
        }

        // Butterfly over the 8 k-phases (lanes with equal p4).
        a0 = addf2(a0, shflx64(a0, 4));  a1 = addf2(a1, shflx64(a1, 4));
        a2 = addf2(a2, shflx64(a2, 4));  a3 = addf2(a3, shflx64(a3, 4));
        a0 = addf2(a0, shflx64(a0, 8));  a1 = addf2(a1, shflx64(a1, 8));
        a2 = addf2(a2, shflx64(a2, 8));  a3 = addf2(a3, shflx64(a3, 8));
        a0 = addf2(a0, shflx64(a0, 16)); a1 = addf2(a1, shflx64(a1, 16));
        a2 = addf2(a2, shflx64(a2, 16)); a3 = addf2(a3, shflx64(a3, 16));

        // Gather: lane (sel<16) takes pair 'sel' from lane src = sel>>2.
        ull v0 = __shfl_sync(0xffffffffu, a0, src);
        ull v1 = __shfl_sync(0xffffffffu, a1, src);
        ull v2 = __shfl_sync(0xffffffffu, a2, src);
        ull v3 = __shfl_sync(0xffffffffu, a3, src);
        ull v  = (sel & 2) ? ((sel & 1) ? v3 : v2) : ((sel & 1) ? v1 : v0);

        if (l < 16) {
            float2 hv = unpk(v);
            float2 hp = *(const float2*)&hrW[ej];          // h_prev from smem
            float g = (sinf((float)t * per + shf) + 1.f) * 0.5f;
            float2 y;
            y.x = (1.f - g) * tanhf(uv.x + hv.x) + g * hp.x;
            y.y = (1.f - g) * tanhf(uv.y + hv.y) + g * hp.y;
            *(float2*)&out[ob] = y;
            *(float2*)&g_h[t & 1][gr * DOUT + ej] = y;
            if (t == T_ - 1)                               // h_final
                *(float2*)&out[YS_ELEMS + gr * DOUT + ej] = y;
        }

        gsync(bid, rowg, colg, (unsigned)(t + 1));
    }
}

// ---------------------------------------------------------------------------
extern "C" void kernel_launch(void* const* d_in, const int* in_sizes, int n_in,
                              void* d_out, int out_size)
{
    (void)in_sizes; (void)n_in; (void)out_size;
    const float* x       = (const float*)d_in[0];
    const float* W_in    = (const float*)d_in[1];
    const float* b_in    = (const float*)d_in[2];
    const float* W_h     = (const float*)d_in[3];
    const float* periods = (const float*)d_in[4];
    const float* shifts  = (const float*)d_in[5];
    float* out = (float*)d_out;

    // Opt-in smem above 48 KB (function-state call, capture-legal).
    cudaFuncSetAttribute(phase2_rnn,
                         cudaFuncAttributeMaxDynamicSharedMemorySize, SMEM2);

    dim3 g1(DOUT / 64, (B_ * T_) / 128);       // (16, 256)
    phase1_gemm<<<g1, 256>>>(x, W_in, b_in, out);
    phase2_rnn<<<NB2, 512, SMEM2>>>(W_h, periods, shifts, out);
}

// round 13
// speedup vs baseline: 1.5090x; 1.5090x over previous
#include <cuda_runtime.h>
#include <cuda_bf16.h>
#include <math.h>

// Problem shape (fixed by the dataset):
//   B=64, T=512, D_in=256, D_out=1024, M=8 (module_size=128)
// KEY STRUCTURE: h@W_h never mixes batch rows, and each row-group's CTAs
// read/write ONLY their own rows (h, u, ys, h_final). So phase 2 runs as
// 2 FULLY INDEPENDENT groups of 64 CTAs (no global barrier at all):
//   CTA = 32 rows x 16 cols, warp = 64-k slice, lane = row.
//   h loads: LDG.32, 128B/warp coalesced. W: 4 uniform-address (broadcast)
//   LDS.128 per k -- the R5/R10-proven cheap pattern (R11's per-lane LDS
//   addressing was the 7200us regression; reverted).
//   Tail: full-512-thread 16-partial tree reduction; per-group flag barrier.

#define B_      64
#define T_      512
#define DIN     256
#define DOUT    1024
#define BSTR    ((size_t)T_ * DOUT)
#define YS_ELEMS ((size_t)B_ * T_ * DOUT)

typedef unsigned long long ull;

// ---------------------------------------------------------------------------
// Packed-fp32 helpers (Blackwell f32x2)
// ---------------------------------------------------------------------------
__device__ __forceinline__ ull dupf(float x) {
    ull r;
    asm("mov.b64 %0, {%1, %1};" : "=l"(r) : "f"(x));
    return r;
}
__device__ __forceinline__ void ffma2(ull& d, ull a, ull b) {
    asm("fma.rn.f32x2 %0, %1, %2, %0;" : "+l"(d) : "l"(a), "l"(b));
}
__device__ __forceinline__ ull addf2(ull a, ull b) {
    ull r;
    asm("add.rn.f32x2 %0, %1, %2;" : "=l"(r) : "l"(a), "l"(b));
    return r;
}

// ---------------------------------------------------------------------------
// Phase 1: u = X @ W_in + b_in     (M=32768, N=1024, K=256)  [unchanged]
// ---------------------------------------------------------------------------
__global__ void __launch_bounds__(256) phase1_gemm(
    const float* __restrict__ X, const float* __restrict__ Win,
    const float* __restrict__ bin, float* __restrict__ out)
{
    __shared__ float As[16 * 132];
    __shared__ float Bs[16 * 68];

    const int tid = threadIdx.x;
    const int tn0 = blockIdx.x * 64;
    const int tm0 = blockIdx.y * 128;
    const int ty  = tid >> 4;
    const int tx  = tid & 15;

    ull acc01[8], acc23[8];
#pragma unroll
    for (int i = 0; i < 8; i++) { acc01[i] = 0ull; acc23[i] = 0ull; }

    const int arow  = tid >> 1;
    const int akoff = (tid & 1) * 8;
    const int bk    = tid >> 4;
    const int bn    = (tid & 15) * 4;

    for (int kc = 0; kc < DIN; kc += 16) {
        const float* ap = &X[(size_t)(tm0 + arow) * DIN + kc + akoff];
        float4 a0 = *(const float4*)(ap);
        float4 a1 = *(const float4*)(ap + 4);
        float4 b0 = *(const float4*)&Win[(size_t)(kc + bk) * DOUT + tn0 + bn];

        __syncthreads();
        As[(akoff + 0) * 132 + arow] = a0.x;
        As[(akoff + 1) * 132 + arow] = a0.y;
        As[(akoff + 2) * 132 + arow] = a0.z;
        As[(akoff + 3) * 132 + arow] = a0.w;
        As[(akoff + 4) * 132 + arow] = a1.x;
        As[(akoff + 5) * 132 + arow] = a1.y;
        As[(akoff + 6) * 132 + arow] = a1.z;
        As[(akoff + 7) * 132 + arow] = a1.w;
        *(float4*)&Bs[bk * 68 + bn] = b0;
        __syncthreads();

#pragma unroll
        for (int kk = 0; kk < 16; kk++) {
            float4 af0 = *(const float4*)&As[kk * 132 + ty * 8];
            float4 af1 = *(const float4*)&As[kk * 132 + ty * 8 + 4];
            ulonglong2 bb = *(const ulonglong2*)&Bs[kk * 68 + tx * 4];
            float a[8] = {af0.x, af0.y, af0.z, af0.w, af1.x, af1.y, af1.z, af1.w};
#pragma unroll
            for (int i = 0; i < 8; i++) {
                ull ad = dupf(a[i]);
                ffma2(acc01[i], ad, bb.x);
                ffma2(acc23[i], ad, bb.y);
            }
        }
    }

    ulonglong2 bp = *(const ulonglong2*)&bin[tn0 + tx * 4];
#pragma unroll
    for (int i = 0; i < 8; i++) {
        ulonglong2 st;
        st.x = addf2(acc01[i], bp.x);
        st.y = addf2(acc23[i], bp.y);
        *(ulonglong2*)&out[(size_t)(tm0 + ty * 8 + i) * DOUT + tn0 + tx * 4] = st;
    }
}

// ---------------------------------------------------------------------------
// Phase 2: 2 independent groups x 64 CTAs.
// CTA (g = bid>>6, colg = bid&63) owns rows [32g,+32) x cols [16*colg,+16).
// ---------------------------------------------------------------------------
#define NB2 128
#define NW2 16                         // warps per CTA (k-slices)
#define KSL 64                         // k per warp
#define PFD 16                         // prefetch ring depth
#define SWFLOATS (DOUT * 16)           // 64 KB: sW[k][16 cols]
#define SPULL    (NW2 * 32 * 9)        // padded partials (9 ull per lane)
#define SMEM2    (SWFLOATS * 4 + SPULL * 8)   // 64 KB + 36 KB = 102400 B

// Transposed hidden state, double-buffered by t parity: g_hT[buf][j*64 + r].
__device__ float g_hT[2][DOUT * B_];

// Per-CTA flags (128B apart); per-group release words (128B apart).
__device__ volatile unsigned g_flag[NB2 * 32];
__device__ volatile unsigned g_gen2[2 * 32];

// Per-group two-hop barrier (proven R5 shape, scoped to 64 CTAs).
// Equality compares + strictly increasing targets => replay-safe.
__device__ __forceinline__ void gsync(int bid, int g, int colg, unsigned target)
{
    __syncthreads();
    if (threadIdx.x == 0) {
        __threadfence();
        g_flag[bid << 5] = target;
    }
    if (colg == 0) {                   // group leader: poll 64 flags, 2/lane
        if (threadIdx.x < 32) {
            const int b0 = (g << 6) + (int)threadIdx.x;
            while (g_flag[b0 << 5] != target ||
                   g_flag[(b0 + 32) << 5] != target) { }
            __syncwarp();
            if (threadIdx.x == 0) {
                __threadfence();
                g_gen2[g << 5] = target;
            }
        }
    } else if (threadIdx.x == 0) {
        while (g_gen2[g << 5] != target) { }
        __threadfence();
    }
    __syncthreads();
}

__global__ void __launch_bounds__(512, 1) phase2_rnn(
    const float* __restrict__ Wh, const float* __restrict__ periods,
    const float* __restrict__ shifts, float* __restrict__ out)
{
    extern __shared__ float smf[];
    float* sW  = smf;                          // [k][16]: W_h[k][j0..j0+15]
    ull*   sPu = (ull*)(smf + SWFLOATS);       // [(w*32+l)*9 + i]
    float* sPf = (float*)sPu;

    const int tid  = threadIdx.x;
    const int bid  = blockIdx.x;
    const int g    = bid >> 6;                 // row-group (0..1)
    const int colg = bid & 63;                 // col-group (0..63)
    const int j0   = colg * 16;                // first of 16 cols
    const int r0   = g * 32;                   // first of 32 rows
    const int w    = tid >> 5;                 // warp = k-slice (0..15)
    const int l    = tid & 31;                 // lane = row r0+l (mainloop)

    // One-time: stage this CTA's 16 W_h columns, k-major (64 B per k).
    for (int i = tid; i < DOUT * 16; i += 512) {
        int k = i >> 4, c = i & 15;
        sW[i] = Wh[(size_t)k * DOUT + j0 + c];
    }
    const float per = periods[colg >> 3];      // 16 cols within one module
    const float shf = shifts[colg >> 3];

    // Tail/epilogue mapping: thread -> (row r, col c); warp = 2 rows x 16 cols.
    const int r  = tid >> 4;                   // 0..31
    const int c  = tid & 15;                   // 0..15
    const int gr = r0 + r;                     // global batch row
    const int gj = j0 + c;                     // global col
    __syncthreads();

    // ---- t = 0: h_prev = 0 -> y = (1-g) * tanh(u). ----
    {
        float g0 = (sinf(shf) + 1.f) * 0.5f;
        size_t ob = (size_t)gr * BSTR + gj;
        float y = (1.f - g0) * tanhf(out[ob]);
        out[ob] = y;
        g_hT[0][gj * B_ + gr] = y;
    }
    gsync(bid, g, colg, 1u);

    const int kbase = w << 6;                  // this warp's K-slice base

    for (int t = 1; t < T_; t++) {
        const float* __restrict__ hsrc = g_hT[(t - 1) & 1];
        float*       __restrict__ hdst = g_hT[t & 1];

        // Hoisted epilogue loads (latency hidden under the mainloop).
        size_t ob = (size_t)gr * BSTR + (size_t)t * DOUT + gj;
        float uv = __ldcg(&out[ob]);
        float hp = __ldcg(&hsrc[gj * B_ + gr]);

        // Mainloop: 64 k per warp; LDG.32 ring (128B/warp coalesced);
        // W via 4 uniform-address (broadcast) LDS.128 per k.
        const float* hs = hsrc + (kbase << 6) + r0 + l;
        ull a0 = 0, a1 = 0, a2 = 0, a3 = 0, a4 = 0, a5 = 0, a6 = 0, a7 = 0;
        float hbuf[PFD];
#pragma unroll
        for (int j = 0; j < PFD; j++) hbuf[j] = __ldcg(hs + (j << 6));

#pragma unroll
        for (int kk = 0; kk < KSL; kk += PFD) {
#pragma unroll
            for (int j = 0; j < PFD; j++) {
                float hq = hbuf[j];
                const int knext = kk + PFD + j;
                if (knext < KSL) hbuf[j] = __ldcg(hs + (knext << 6));
                const ulonglong2* wp =
                    (const ulonglong2*)(sW + ((kbase + kk + j) << 4));
                ulonglong2 wA = wp[0];         // cols 0..3   (broadcast)
                ulonglong2 wB = wp[1];         // cols 4..7
                ulonglong2 wC = wp[2];         // cols 8..11
                ulonglong2 wD = wp[3];         // cols 12..15
                ull hd = dupf(hq);
                ffma2(a0, hd, wA.x); ffma2(a1, hd, wA.y);
                ffma2(a2, hd, wB.x); ffma2(a3, hd, wB.y);
                ffma2(a4, hd, wC.x); ffma2(a5, hd, wC.y);
                ffma2(a6, hd, wD.x); ffma2(a7, hd, wD.y);
            }
        }

        // Partials: lane l = row, 8 ull = 16 cols; 9-ull pitch (pad) caps
        // bank conflicts at 2-way.
        {
            ull* p = sPu + ((w << 5) + l) * 9;
            p[0] = a0; p[1] = a1; p[2] = a2; p[3] = a3;
            p[4] = a4; p[5] = a5; p[6] = a6; p[7] = a7;
        }
        __syncthreads();

        // Full-width tail: thread (r, c) tree-sums 16 partials.
        float p[NW2];
#pragma unroll
        for (int w2 = 0; w2 < NW2; w2++)
            p[w2] = sPf[((((w2 << 5) + r) * 9 + (c >> 1)) << 1) + (c & 1)];
        float s01 = p[0] + p[1],   s23 = p[2] + p[3];
        float s45 = p[4] + p[5],   s67 = p[6] + p[7];
        float s89 = p[8] + p[9],   sab = p[10] + p[11];
        float scd = p[12] + p[13], sef = p[14] + p[15];
        float hv = ((s01 + s23) + (s45 + s67)) + ((s89 + sab) + (scd + sef));

        float gg = (sinf((float)t * per + shf) + 1.f) * 0.5f;
        float y = (1.f - gg) * tanhf(uv + hv) + gg * hp;
        out[ob] = y;
        hdst[gj * B_ + gr] = y;
        if (t == T_ - 1)                        // h_final = ys[:, T-1, :]
            out[YS_ELEMS + (size_t)gr * DOUT + gj] = y;

        gsync(bid, g, colg, (unsigned)(t + 1)); // also fences sPu reuse
    }
}

// ---------------------------------------------------------------------------
extern "C" void kernel_launch(void* const* d_in, const int* in_sizes, int n_in,
                              void* d_out, int out_size)
{
    (void)in_sizes; (void)n_in; (void)out_size;
    const float* x       = (const float*)d_in[0];
    const float* W_in    = (const float*)d_in[1];
    const float* b_in    = (const float*)d_in[2];
    const float* W_h     = (const float*)d_in[3];
    const float* periods = (const float*)d_in[4];
    const float* shifts  = (const float*)d_in[5];
    float* out = (float*)d_out;

    // Opt-in smem above 48 KB (function-state call, capture-legal).
    cudaFuncSetAttribute(phase2_rnn,
                         cudaFuncAttributeMaxDynamicSharedMemorySize, SMEM2);

    dim3 g1(DOUT / 64, (B_ * T_) / 128);       // (16, 256)
    phase1_gemm<<<g1, 256>>>(x, W_in, b_in, out);
    phase2_rnn<<<NB2, 512, SMEM2>>>(W_h, periods, shifts, out);
}

// round 15
// speedup vs baseline: 1.8383x; 1.2182x over previous
#include <cuda_runtime.h>
#include <cuda_bf16.h>
#include <math.h>

// Problem shape (fixed by the dataset):
//   B=64, T=512, D_in=256, D_out=1024, M=8 (module_size=128)
// Phase 1: u = x@W_in + b_in into the ys region of d_out (f32x2 GEMM).
// Phase 2: persistent 128 CTAs x 512 threads, R10-proven structure
//   (CTA = 8 cols x 64 rows, 16 k-slice warps, flag-tree barrier), with the
//   lane microtile enlarged to 4 rows x 4 cols:
//   per warp-k = 1 LDG.128 (4 h rows) + 1 16B LDS (4 W cols, half-warp
//   uniform) + 8 FFMA2  ->  LSU 8 cyc < FFMA2 16 cyc: FMA-bound at last.
//   (R12 ran 5 mem-ops per 8 FFMA2 and was MIO-bound at the nw>=4 crossbar
//   floor of 4 cyc/op -- that was the 4772us regression.)

#define B_      64
#define T_      512
#define DIN     256
#define DOUT    1024
#define BSTR    ((size_t)T_ * DOUT)
#define YS_ELEMS ((size_t)B_ * T_ * DOUT)

typedef unsigned long long ull;

// ---------------------------------------------------------------------------
// Packed-fp32 helpers (Blackwell f32x2)
// ---------------------------------------------------------------------------
__device__ __forceinline__ ull dupf(float x) {
    ull r;
    asm("mov.b64 %0, {%1, %1};" : "=l"(r) : "f"(x));
    return r;
}
__device__ __forceinline__ void ffma2(ull& d, ull a, ull b) {
    asm("fma.rn.f32x2 %0, %1, %2, %0;" : "+l"(d) : "l"(a), "l"(b));
}
__device__ __forceinline__ ull addf2(ull a, ull b) {
    ull r;
    asm("add.rn.f32x2 %0, %1, %2;" : "=l"(r) : "l"(a), "l"(b));
    return r;
}

// ---------------------------------------------------------------------------
// Phase 1: u = X @ W_in + b_in     (M=32768, N=1024, K=256)  [unchanged]
// ---------------------------------------------------------------------------
__global__ void __launch_bounds__(256) phase1_gemm(
    const float* __restrict__ X, const float* __restrict__ Win,
    const float* __restrict__ bin, float* __restrict__ out)
{
    __shared__ float As[16 * 132];
    __shared__ float Bs[16 * 68];

    const int tid = threadIdx.x;
    const int tn0 = blockIdx.x * 64;
    const int tm0 = blockIdx.y * 128;
    const int ty  = tid >> 4;
    const int tx  = tid & 15;

    ull acc01[8], acc23[8];
#pragma unroll
    for (int i = 0; i < 8; i++) { acc01[i] = 0ull; acc23[i] = 0ull; }

    const int arow  = tid >> 1;
    const int akoff = (tid & 1) * 8;
    const int bk    = tid >> 4;
    const int bn    = (tid & 15) * 4;

    for (int kc = 0; kc < DIN; kc += 16) {
        const float* ap = &X[(size_t)(tm0 + arow) * DIN + kc + akoff];
        float4 a0 = *(const float4*)(ap);
        float4 a1 = *(const float4*)(ap + 4);
        float4 b0 = *(const float4*)&Win[(size_t)(kc + bk) * DOUT + tn0 + bn];

        __syncthreads();
        As[(akoff + 0) * 132 + arow] = a0.x;
        As[(akoff + 1) * 132 + arow] = a0.y;
        As[(akoff + 2) * 132 + arow] = a0.z;
        As[(akoff + 3) * 132 + arow] = a0.w;
        As[(akoff + 4) * 132 + arow] = a1.x;
        As[(akoff + 5) * 132 + arow] = a1.y;
        As[(akoff + 6) * 132 + arow] = a1.z;
        As[(akoff + 7) * 132 + arow] = a1.w;
        *(float4*)&Bs[bk * 68 + bn] = b0;
        __syncthreads();

#pragma unroll
        for (int kk = 0; kk < 16; kk++) {
            float4 af0 = *(const float4*)&As[kk * 132 + ty * 8];
            float4 af1 = *(const float4*)&As[kk * 132 + ty * 8 + 4];
            ulonglong2 bb = *(const ulonglong2*)&Bs[kk * 68 + tx * 4];
            float a[8] = {af0.x, af0.y, af0.z, af0.w, af1.x, af1.y, af1.z, af1.w};
#pragma unroll
            for (int i = 0; i < 8; i++) {
                ull ad = dupf(a[i]);
                ffma2(acc01[i], ad, bb.x);
                ffma2(acc23[i], ad, bb.y);
            }
        }
    }

    ulonglong2 bp = *(const ulonglong2*)&bin[tn0 + tx * 4];
#pragma unroll
    for (int i = 0; i < 8; i++) {
        ulonglong2 st;
        st.x = addf2(acc01[i], bp.x);
        st.y = addf2(acc23[i], bp.y);
        *(ulonglong2*)&out[(size_t)(tm0 + ty * 8 + i) * DOUT + tn0 + tx * 4] = st;
    }
}

// ---------------------------------------------------------------------------
// Phase 2: persistent recurrence. 128 CTAs x 512 threads, 8 cols per CTA.
// ---------------------------------------------------------------------------
#define NB2 128
#define NW2 16                        // warps per CTA (k-slices)
#define KSL 64                        // k per warp
#define PFD 8                         // prefetch ring depth (float4 x 8)
#define SMEM2 (DOUT * 4 * 8 + NW2 * 32 * 9 * 8)   // 32 KB sW + 36 KB sP

// Transposed hidden state, double-buffered by t parity: g_hT[buf][j*64 + r].
__device__ float g_hT[2][DOUT * B_];

// Flag-tree grid barrier state (R5/R10-proven). Per-CTA flags 128B apart.
__device__ volatile unsigned g_flag[NB2 * 32];
__device__ volatile unsigned g_gen2;

// Grid barrier: CTA stores its step to a private flag; CTA 0 warp 0 polls
// all flags and broadcasts via a single word (L2-friendly same-address spin
// for the other 127 CTAs). Equality compares + strictly increasing targets
// make this replay-safe.
__device__ __forceinline__ void gsync(int bid, unsigned target)
{
    __syncthreads();
    if (threadIdx.x < 32) {
        if (threadIdx.x == 0) {
            __threadfence();
            g_flag[bid << 5] = target;
        }
        if (bid == 0) {
            bool done;
            do {
                done = true;
#pragma unroll
                for (int c = threadIdx.x; c < NB2; c += 32)
                    if (g_flag[c << 5] != target) done = false;
            } while (!__all_sync(0xffffffffu, done));
            if (threadIdx.x == 0) {
                __threadfence();
                g_gen2 = target;
            }
        } else if (threadIdx.x == 0) {
            while (g_gen2 != target) { }
            __threadfence();
        }
    }
    __syncthreads();
}

__global__ void __launch_bounds__(512, 1) phase2_rnn(
    const float* __restrict__ Wh, const float* __restrict__ periods,
    const float* __restrict__ shifts, float* __restrict__ out)
{
    extern __shared__ char smem_raw[];
    float2* sW  = (float2*)smem_raw;                 // [k][col-pair], 32 KB
    ull*    sPu = (ull*)(smem_raw + DOUT * 4 * 8);   // [(w*32+l)*9+i], 36 KB
    float*  sPf = (float*)sPu;

    const int tid = threadIdx.x;
    const int bid = blockIdx.x;
    const int j0  = bid * 8;
    const int w   = tid >> 5;             // warp = k-slice (0..15)
    const int l   = tid & 31;
    const int li  = l & 15;               // row block: rows 4*li..4*li+3
    const int hf  = l >> 4;               // col half: cols j0+4*hf..+3

    // One-time: this CTA's 8 W_h columns as col-pairs.
    for (int i = tid; i < DOUT * 4; i += 512) {
        int k = i >> 2, cp = i & 3;
        sW[i] = make_float2(Wh[(size_t)k * DOUT + j0 + 2 * cp],
                            Wh[(size_t)k * DOUT + j0 + 2 * cp + 1]);
    }
    const float per = periods[bid >> 4];
    const float shf = shifts[bid >> 4];

    // Tail/epilogue mapping: thread -> one scalar (row er, col ec).
    const int er = tid >> 3;              // 0..63 (batch row)
    const int ec = tid & 7;               // 0..7  (col within CTA)
    const int gj = j0 + ec;               // global col
    // Source coordinates in sP: producing lane, ull index, half.
    const int s_lane = ((ec >> 2) << 4) + (er >> 2);          // hf*16 + li
    const int s_ull  = ((er & 3) << 1) + ((ec & 3) >> 1);     // r*2 + cu
    const int s_half = ec & 1;
    __syncthreads();

    // ---- t = 0: h_prev = 0 -> y = (1-g) * tanh(u). ----
    {
        float g0 = (sinf(shf) + 1.f) * 0.5f;
        size_t ob = (size_t)er * BSTR + gj;
        float y = (1.f - g0) * tanhf(out[ob]);
        out[ob] = y;
        g_hT[0][gj * B_ + er] = y;
    }
    gsync(bid, 1u);

    const int kbase = w << 6;             // this warp's K-slice base

    for (int t = 1; t < T_; t++) {
        const float* __restrict__ hsrc = g_hT[(t - 1) & 1];
        float*       __restrict__ hdst = g_hT[t & 1];

        // Hoisted epilogue loads (latency hidden under the mainloop).
        size_t ob = (size_t)er * BSTR + (size_t)t * DOUT + gj;
        float uv = __ldcg(&out[ob]);
        float hp = __ldcg(&hsrc[gj * B_ + er]);

        // Mainloop: 64 k per warp. Lane: 4 rows (LDG.128) x 4 cols (16B LDS,
        // uniform per half-warp). 8 FFMA2 per k vs 2 mem instrs -> FMA-bound.
        const float* hs = hsrc + (kbase << 6) + (li << 2);
        ull a[8];
#pragma unroll
        for (int i = 0; i < 8; i++) a[i] = 0ull;
        float4 hbuf[PFD];
#pragma unroll
        for (int j = 0; j < PFD; j++)
            hbuf[j] = __ldcg((const float4*)(hs + (j << 6)));

#pragma unroll
        for (int kk = 0; kk < KSL; kk += PFD) {
#pragma unroll
            for (int j = 0; j < PFD; j++) {
                float4 h4 = hbuf[j];
                const int knext = kk + PFD + j;
                if (knext < KSL)
                    hbuf[j] = __ldcg((const float4*)(hs + (knext << 6)));
                // 16B of W: cols j0+4hf .. j0+4hf+3 at k.
                ulonglong2 wv = *(const ulonglong2*)
                    &sW[((kbase + kk + j) << 2) + (hf << 1)];
                ull h0 = dupf(h4.x), h1 = dupf(h4.y);
                ull h2 = dupf(h4.z), h3 = dupf(h4.w);
                ffma2(a[0], h0, wv.x); ffma2(a[1], h0, wv.y);   // row 4li+0
                ffma2(a[2], h1, wv.x); ffma2(a[3], h1, wv.y);   // row 4li+1
                ffma2(a[4], h2, wv.x); ffma2(a[5], h2, wv.y);   // row 4li+2
                ffma2(a[6], h3, wv.x); ffma2(a[7], h3, wv.y);   // row 4li+3
            }
        }

        // Partials: 8 ull per lane, 9-ull pitch (pad) to cap conflicts.
        {
            ull* p = sPu + ((w << 5) + l) * 9;
            p[0] = a[0]; p[1] = a[1]; p[2] = a[2]; p[3] = a[3];
            p[4] = a[4]; p[5] = a[5]; p[6] = a[6]; p[7] = a[7];
        }
        __syncthreads();

        // Full-width tail: thread (er, ec) tree-sums its 16 partials.
        float p[NW2];
#pragma unroll
        for (int w2 = 0; w2 < NW2; w2++)
            p[w2] = sPf[((((w2 << 5) + s_lane) * 9 + s_ull) << 1) + s_half];
        float s01 = p[0] + p[1],   s23 = p[2] + p[3];
        float s45 = p[4] + p[5],   s67 = p[6] + p[7];
        float s89 = p[8] + p[9],   sab = p[10] + p[11];
        float scd = p[12] + p[13], sef = p[14] + p[15];
        float hv = ((s01 + s23) + (s45 + s67)) + ((s89 + sab) + (scd + sef));

        float gg = (sinf((float)t * per + shf) + 1.f) * 0.5f;
        float y = (1.f - gg) * tanhf(uv + hv) + gg * hp;
        out[ob] = y;
        hdst[gj * B_ + er] = y;
        if (t == T_ - 1)                  // h_final = ys[:, T-1, :]
            out[YS_ELEMS + (size_t)er * DOUT + gj] = y;

        gsync(bid, (unsigned)(t + 1));    // also fences sPu reuse
    }
}

// ---------------------------------------------------------------------------
extern "C" void kernel_launch(void* const* d_in, const int* in_sizes, int n_in,
                              void* d_out, int out_size)
{
    (void)in_sizes; (void)n_in; (void)out_size;
    const float* x       = (const float*)d_in[0];
    const float* W_in    = (const float*)d_in[1];
    const float* b_in    = (const float*)d_in[2];
    const float* W_h     = (const float*)d_in[3];
    const float* periods = (const float*)d_in[4];
    const float* shifts  = (const float*)d_in[5];
    float* out = (float*)d_out;

    // Opt-in smem above 48 KB (function-state call, capture-legal).
    cudaFuncSetAttribute(phase2_rnn,
                         cudaFuncAttributeMaxDynamicSharedMemorySize, SMEM2);

    dim3 g1(DOUT / 64, (B_ * T_) / 128);       // (16, 256)
    phase1_gemm<<<g1, 256>>>(x, W_in, b_in, out);
    phase2_rnn<<<NB2, 512, SMEM2>>>(W_h, periods, shifts, out);
}